// round 15
// baseline (speedup 1.0000x reference)
#include <cuda_runtime.h>
#include <cstdint>

// out[b,c,h,w] = max over 4 directional 3x3 Laplacians (zero-padded).
// out = max(s0,s1,s2,s3) - 2*c  (shared center term -> single FFMA).
// 256-bit era: TW=8 px/thread via ld/st.global.v8.b32 (sm_103a supports it),
// halving LSU dispatches, L1 wavefronts and issue slots per pixel.
// 64-thread blocks = one full row; RPT=16 -> grid 1536 = single wave.
// Depth-1 prefetch (4 rotating 10-float windows); halos deferred-shuffled
// one iteration after load; single merged predicated edge LDG per row.

#define W   512
#define H   512
#define RPT 16   // rows per thread

__device__ __forceinline__ void ldg256(const float* p, float a[8]) {
    uint32_t r0, r1, r2, r3, r4, r5, r6, r7;
    asm("ld.global.nc.v8.b32 {%0,%1,%2,%3,%4,%5,%6,%7}, [%8];"
        : "=r"(r0), "=r"(r1), "=r"(r2), "=r"(r3),
          "=r"(r4), "=r"(r5), "=r"(r6), "=r"(r7)
        : "l"(p));
    a[0] = __uint_as_float(r0); a[1] = __uint_as_float(r1);
    a[2] = __uint_as_float(r2); a[3] = __uint_as_float(r3);
    a[4] = __uint_as_float(r4); a[5] = __uint_as_float(r5);
    a[6] = __uint_as_float(r6); a[7] = __uint_as_float(r7);
}
__device__ __forceinline__ void stg256(float* p, const float a[8]) {
    asm volatile("st.global.v8.b32 [%0], {%1,%2,%3,%4,%5,%6,%7,%8};"
                 :: "l"(p),
                    "r"(__float_as_uint(a[0])), "r"(__float_as_uint(a[1])),
                    "r"(__float_as_uint(a[2])), "r"(__float_as_uint(a[3])),
                    "r"(__float_as_uint(a[4])), "r"(__float_as_uint(a[5])),
                    "r"(__float_as_uint(a[6])), "r"(__float_as_uint(a[7]))
                 : "memory");
}

// Load a[1..8] = x[h][w0..w0+7]; merged predicated edge load into a[0]/a[9]
// (lane 0 takes x[w0-1], lane 31 takes x[w0+8]); interior halos filled later.
__device__ __forceinline__ void load_row(const float* __restrict__ img,
                                         int h, int w0, int lane, float a[10]) {
    if ((unsigned)h >= (unsigned)H) {
        #pragma unroll
        for (int i = 0; i < 10; i++) a[i] = 0.f;
        return;
    }
    const float* row = img + h * W;
    ldg256(row + w0, a + 1);

    float hv = 0.f;
    const bool left  = (lane == 0)  && (w0 > 0);
    const bool right = (lane == 31) && (w0 + 8 < W);
    if (left || right)
        hv = __ldg(row + (left ? (w0 - 1) : (w0 + 8)));
    a[0] = hv;   // valid on lane 0; interior lanes overwritten by finalize
    a[9] = hv;   // valid on lane 31
}

// Fill interior halo slots from neighbor lanes (values loaded one iter ago).
__device__ __forceinline__ void finalize_row(int lane, float a[10]) {
    const float l = __shfl_up_sync(0xffffffffu, a[8], 1);    // lane-1's x[w0-1]
    const float r = __shfl_down_sync(0xffffffffu, a[1], 1);  // lane+1's x[w0+8]
    if (lane != 0)  a[0] = l;
    if (lane != 31) a[9] = r;
}

__global__ __launch_bounds__(64, 16)
void maxlap_kernel(const float* __restrict__ x, float* __restrict__ out) {
    const int tid  = threadIdx.x;
    const int lane = tid & 31;
    const int img  = blockIdx.y;
    const int h0   = blockIdx.x * RPT;
    const int w0   = tid * 8;          // 64 threads cover the full 512 row

    const float* in  = x   + (size_t)img * H * W;
    float*       dst = out + (size_t)img * H * W;

    // Window lifecycle: loaded at iter rr (slot (rr+3)&3), finalized at rr+1,
    // used as b/m/t at rr+1/rr+2/rr+3.
    float win[4][10];
    load_row(in, h0 - 1, w0, lane, win[0]);
    load_row(in, h0,     w0, lane, win[1]);
    load_row(in, h0 + 1, w0, lane, win[2]);
    finalize_row(lane, win[0]);
    finalize_row(lane, win[1]);

    #pragma unroll
    for (int rr = 0; rr < RPT; rr++) {
        if (rr < RPT - 1)
            load_row(in, h0 + rr + 2, w0, lane, win[(rr + 3) & 3]);  // prefetch

        finalize_row(lane, win[(rr + 2) & 3]);  // b row, loaded last iteration

        const float* t = win[ rr      & 3];
        const float* m = win[(rr + 1) & 3];
        const float* b = win[(rr + 2) & 3];

        float o[8];
        #pragma unroll
        for (int i = 0; i < 8; i++) {
            const float s0 = m[i]     + m[i + 2];
            const float s1 = t[i + 1] + b[i + 1];
            const float s2 = t[i + 2] + b[i];
            const float s3 = t[i]     + b[i + 2];
            const float ms = fmaxf(fmaxf(s0, s1), fmaxf(s2, s3));
            o[i] = fmaf(-2.f, m[i + 1], ms);
        }
        stg256(dst + (h0 + rr) * W + w0, o);
    }
}

extern "C" void kernel_launch(void* const* d_in, const int* in_sizes, int n_in,
                              void* d_out, int out_size) {
    const float* x = (const float*)d_in[0];
    float* out = (float*)d_out;

    const int n_img = in_sizes[0] / (H * W);  // B*C = 48

    dim3 block(W / 8);               // 64 threads = one full row (8 px each)
    dim3 grid(H / RPT, n_img);       // 32 x 48 = 1536 blocks (single wave)
    maxlap_kernel<<<grid, block>>>(x, out);
}